// round 3
// baseline (speedup 1.0000x reference)
#include <cuda_runtime.h>

#define VV   400000
#define DD   200
#define CC   45
#define BSN  4096      // B*S
#define SS   128       // S (window padding is per-sequence)
#define KN   12
#define KC   10
#define KT   22
#define F5   1000      // 5*D

// ---- kernel 2 tiling ----
#define TT    32       // tokens per block  (4096/32 = 128 blocks; 32 divides 128)
#define CPAD  48       // c padded to multiple of 4
#define WS    1002     // padded W row stride (floats)
#define KSP   8        // k-splits per output tile (lanes tid&7)
#define NT2   768      // threads (24 warps): 96 tiles x 8 k-splits

// scratch: feat [4096, 200]
__device__ float g_feat[BSN * DD];

// ============================================================
// Kernel 1: masked gather + mean  -> g_feat
// ============================================================
__global__ __launch_bounds__(128) void feat_kernel(
    const int* __restrict__ ng_ids, const int* __restrict__ ng_mask,
    const int* __restrict__ cx_ids, const int* __restrict__ cx_mask,
    const float* __restrict__ embed)
{
    const int tok = blockIdx.x;
    const int tid = threadIdx.x;

    __shared__ int raw_ids[KT], raw_msk[KT];
    __shared__ int s_ids[KT];
    __shared__ int s_n;
    __shared__ float s_inv;

    if (tid < KN) {
        raw_ids[tid] = ng_ids[tok * KN + tid];
        raw_msk[tid] = ng_mask[tok * KN + tid];
    } else if (tid < KT) {
        const int j = tid - KN;
        raw_ids[tid] = cx_ids[tok * KC + j];
        raw_msk[tid] = cx_mask[tok * KC + j];
    }
    __syncthreads();

    if (tid == 0) {
        int n = 0;
        #pragma unroll
        for (int i = 0; i < KT; i++)
            if (raw_msk[i]) s_ids[n++] = raw_ids[i];
        s_n = n;
        s_inv = 1.0f / (float)(n > 0 ? n : 1);
    }
    __syncthreads();

    const int n = s_n;
    const float inv = s_inv;

    if (tid < DD / 2) {
        float sx = 0.f, sy = 0.f;
        #pragma unroll 4
        for (int i = 0; i < n; i++) {
            const long long row = (long long)s_ids[i] * DD;
            const float2 v = *(const float2*)&embed[row + tid * 2];
            sx += v.x; sy += v.y;
        }
        *(float2*)&g_feat[(long long)tok * DD + tid * 2] = make_float2(sx * inv, sy * inv);
    }
}

// ============================================================
// Kernel 2: windowed matmul  out[t,c] = b[c] + dot(window(t), W[c,:])
// 4c x 4t register tile, packed f32x2 FMA, 8-way k split (shuffle reduce),
// 768 threads = 24 warps/SM for latency hiding.
// ============================================================
__device__ __forceinline__ void ffma2(unsigned long long& d,
                                      unsigned long long a,
                                      unsigned long long b)
{
    asm volatile("fma.rn.f32x2 %0, %1, %2, %0;" : "+l"(d) : "l"(a), "l"(b));
}

extern __shared__ float smem2[];

__global__ __launch_bounds__(NT2) void gemm_kernel(
    const float* __restrict__ W, const float* __restrict__ bias,
    float* __restrict__ out)
{
    float* sW = smem2;                 // CPAD * WS floats
    float* sX = smem2 + CPAD * WS;     // (TT+4) * DD floats (halo rows)

    const int tid = threadIdx.x;
    const int t0  = blockIdx.x * TT;
    const int b0  = t0 / SS;           // sequence index of this tile

    // ---- load W into padded shared rows (float2 granularity) ----
    {
        unsigned long long*       sW2 = (unsigned long long*)sW;
        const unsigned long long* W2  = (const unsigned long long*)W;
        const int total = (CC * F5) / 2;                // 22500 float2
        for (int i = tid; i < total; i += NT2) {
            const int c = i / (F5 / 2);
            const int f = i % (F5 / 2);
            sW2[c * (WS / 2) + f] = W2[i];
        }
        const int padtot = (CPAD - CC) * (WS / 2);
        for (int i = tid; i < padtot; i += NT2)
            sW2[CC * (WS / 2) + i] = 0ull;
        for (int i = tid; i < CC; i += NT2)
            sW2[i * (WS / 2) + (F5 / 2)] = 0ull;
    }

    // ---- load X tile with +-2 halo rows, zero outside this sequence ----
    {
        float4*       sX4   = (float4*)sX;
        const float4* feat4 = (const float4*)g_feat;
        const int total = ((TT + 4) * DD) / 4;          // 1800 float4
        for (int i = tid; i < total; i += NT2) {
            const int row = i / (DD / 4);
            const int col = i % (DD / 4);
            const int g = t0 + row - 2;
            const bool ok = ((g >> 7) == b0);   // same 128-token sequence only
            sX4[i] = ok ? feat4[(long long)g * (DD / 4) + col]
                        : make_float4(0.f, 0.f, 0.f, 0.f);
        }
    }
    __syncthreads();

    // thread decomposition: 96 tiles x 8 k-splits
    const int ks    = tid & 7;        // k-split lane (groups of 8 within warp)
    const int tile  = tid >> 3;       // 0..95
    const int cg    = tile % 12;      // c group (4 c's)
    const int tg    = tile / 12;      // t group (4 t's), 0..7
    const int cbase = cg * 4;
    const int tbase = tg * 4;

    unsigned long long acc[4][4];
    #pragma unroll
    for (int i = 0; i < 4; i++)
        #pragma unroll
        for (int j = 0; j < 4; j++) acc[i][j] = 0ull;

    const unsigned long long* sW2 = (const unsigned long long*)sW;
    const unsigned long long* sX2 = (const unsigned long long*)sX;

    // uneven split of 500 float2: first 4 splits get 63, last 4 get 62
    const int len = 63 - (ks >> 2);                         // 63 or 62
    const int k0  = (ks < 4) ? ks * 63 : 252 + (ks - 4) * 62;

    #pragma unroll 1
    for (int kk = k0; kk < k0 + len; kk++) {
        unsigned long long w[4], x[4];
        #pragma unroll
        for (int j = 0; j < 4; j++) w[j] = sW2[(cbase + j) * (WS / 2) + kk];
        #pragma unroll
        for (int i = 0; i < 4; i++) x[i] = sX2[(tbase + i) * (DD / 2) + kk];
        #pragma unroll
        for (int i = 0; i < 4; i++)
            #pragma unroll
            for (int j = 0; j < 4; j++)
                ffma2(acc[i][j], x[i], w[j]);
    }

    // ---- reduce packed halves + across 8 k-splits (adjacent lanes) ----
    #pragma unroll
    for (int i = 0; i < 4; i++) {
        #pragma unroll
        for (int j = 0; j < 4; j++) {
            const unsigned long long a = acc[i][j];
            float v = __uint_as_float((unsigned)(a & 0xffffffffull)) +
                      __uint_as_float((unsigned)(a >> 32));
            v += __shfl_xor_sync(0xffffffffu, v, 1);
            v += __shfl_xor_sync(0xffffffffu, v, 2);
            v += __shfl_xor_sync(0xffffffffu, v, 4);
            if (ks == 0) {
                const int c = cbase + j;
                if (c < CC)
                    out[(long long)(t0 + tbase + i) * CC + c] = v + bias[c];
            }
        }
    }
}

// ============================================================
extern "C" void kernel_launch(void* const* d_in, const int* in_sizes, int n_in,
                              void* d_out, int out_size)
{
    const int*   ng_ids  = (const int*)d_in[0];
    const int*   ng_mask = (const int*)d_in[1];
    const int*   cx_ids  = (const int*)d_in[2];
    const int*   cx_mask = (const int*)d_in[3];
    const float* embed   = (const float*)d_in[4];
    const float* W       = (const float*)d_in[5];
    const float* bias    = (const float*)d_in[6];
    float*       out     = (float*)d_out;

    feat_kernel<<<BSN, 128>>>(ng_ids, ng_mask, cx_ids, cx_mask, embed);

    const size_t smem = (size_t)(CPAD * WS + (TT + 4) * DD) * sizeof(float); // 221,184 B
    cudaFuncSetAttribute(gemm_kernel, cudaFuncAttributeMaxDynamicSharedMemorySize, (int)smem);
    gemm_kernel<<<BSN / TT, NT2, smem>>>(W, bias, out);
}

// round 4
// speedup vs baseline: 1.1590x; 1.1590x over previous
#include <cuda_runtime.h>

#define VV   400000
#define DD   200
#define CC   45
#define BSN  4096      // B*S
#define SS   128       // S (window padding is per-sequence)
#define KN   12
#define KC   10
#define KT   22
#define F5   1000      // 5*D
#define KK2  500       // F5/2 float2 per window

// ---- kernel 2 tiling ----
#define TT    32       // tokens per block (4096/32 = 128 blocks; 32 divides 128)
#define CPAD  48
#define WS    1002     // padded W row stride (floats) -> 501 float2
#define NT2   384      // 12 warps: 6 c-groups x 2 t-halves x 32 lanes

// scratch: feat [4096, 200]
__device__ float g_feat[BSN * DD];

// ============================================================
// Kernel 1: masked gather + mean  -> g_feat
// ============================================================
__global__ __launch_bounds__(128) void feat_kernel(
    const int* __restrict__ ng_ids, const int* __restrict__ ng_mask,
    const int* __restrict__ cx_ids, const int* __restrict__ cx_mask,
    const float* __restrict__ embed)
{
    const int tok = blockIdx.x;
    const int tid = threadIdx.x;

    __shared__ int raw_ids[KT], raw_msk[KT];
    __shared__ int s_ids[KT];
    __shared__ int s_n;
    __shared__ float s_inv;

    if (tid < KN) {
        raw_ids[tid] = ng_ids[tok * KN + tid];
        raw_msk[tid] = ng_mask[tok * KN + tid];
    } else if (tid < KT) {
        const int j = tid - KN;
        raw_ids[tid] = cx_ids[tok * KC + j];
        raw_msk[tid] = cx_mask[tok * KC + j];
    }
    __syncthreads();

    if (tid == 0) {
        int n = 0;
        #pragma unroll
        for (int i = 0; i < KT; i++)
            if (raw_msk[i]) s_ids[n++] = raw_ids[i];
        s_n = n;
        s_inv = 1.0f / (float)(n > 0 ? n : 1);
    }
    __syncthreads();

    const int n = s_n;
    const float inv = s_inv;

    if (tid < DD / 2) {
        float sx = 0.f, sy = 0.f;
        #pragma unroll 4
        for (int i = 0; i < n; i++) {
            const long long row = (long long)s_ids[i] * DD;
            const float2 v = *(const float2*)&embed[row + tid * 2];
            sx += v.x; sy += v.y;
        }
        *(float2*)&g_feat[(long long)tok * DD + tid * 2] = make_float2(sx * inv, sy * inv);
    }
}

// ============================================================
// Kernel 2: windowed matmul, crossbar-optimal layout
//   thread tile 8c x 4t, warp = 8 ksplit-lanes x 4 t-groups (same c's)
//   w-loads: 8 consecutive float2, broadcast across t-groups -> 1 phase
//   x-loads: bank pattern (8g+2ks)%32 -> exact 2-phase floor
// ============================================================
__device__ __forceinline__ void ffma2(unsigned long long& d,
                                      unsigned long long a,
                                      unsigned long long b)
{
    asm volatile("fma.rn.f32x2 %0, %1, %2, %0;" : "+l"(d) : "l"(a), "l"(b));
}

extern __shared__ float smem2[];

__global__ __launch_bounds__(NT2) void gemm_kernel(
    const float* __restrict__ W, const float* __restrict__ bias,
    float* __restrict__ out)
{
    float* sW = smem2;                 // CPAD * WS floats
    float* sX = smem2 + CPAD * WS;     // (TT+4) * DD floats (halo rows)

    const int tid = threadIdx.x;
    const int t0  = blockIdx.x * TT;
    const int b0  = t0 / SS;           // sequence index of this tile

    // ---- load W into padded shared rows (float2 granularity) ----
    {
        unsigned long long*       sW2 = (unsigned long long*)sW;
        const unsigned long long* W2  = (const unsigned long long*)W;
        const int total = (CC * F5) / 2;                // 22500 float2
        for (int i = tid; i < total; i += NT2) {
            const int c = i / (F5 / 2);
            const int f = i % (F5 / 2);
            sW2[c * (WS / 2) + f] = W2[i];
        }
        const int padtot = (CPAD - CC) * (WS / 2);
        for (int i = tid; i < padtot; i += NT2)
            sW2[CC * (WS / 2) + i] = 0ull;
        for (int i = tid; i < CC; i += NT2)
            sW2[i * (WS / 2) + (F5 / 2)] = 0ull;
    }

    // ---- load X tile with +-2 halo rows, zero outside this sequence ----
    {
        float4*       sX4   = (float4*)sX;
        const float4* feat4 = (const float4*)g_feat;
        const int total = ((TT + 4) * DD) / 4;          // 1800 float4
        for (int i = tid; i < total; i += NT2) {
            const int row = i / (DD / 4);
            const int col = i % (DD / 4);
            const int g = t0 + row - 2;
            const bool ok = ((g >> 7) == b0);   // same 128-token sequence only
            sX4[i] = ok ? feat4[(long long)g * (DD / 4) + col]
                        : make_float4(0.f, 0.f, 0.f, 0.f);
        }
    }
    __syncthreads();

    // ---- decomposition ----
    const int lane = tid & 31;
    const int wrp  = tid >> 5;        // 0..11
    const int ks   = lane & 7;        // k-split (interleaved: kk = ks + 8s)
    const int g    = lane >> 3;       // t-group within warp, 0..3
    const int cg   = wrp % 6;         // c group (8 c's)
    const int th   = wrp / 6;         // t half (16 tokens)
    const int cbase  = cg * 8;
    const int ltbase = th * 16 + g;   // thread's tokens: ltbase + 4*i (stride 4, base stride 1 over g)

    unsigned long long acc[4][8];
    #pragma unroll
    for (int i = 0; i < 4; i++)
        #pragma unroll
        for (int j = 0; j < 8; j++) acc[i][j] = 0ull;

    const unsigned long long* sW2 = (const unsigned long long*)sW;
    const unsigned long long* sX2 = (const unsigned long long*)sX;

    const unsigned long long* wp = sW2 + (long long)cbase * (WS / 2) + ks;
    const unsigned long long* xp = sX2 + (long long)ltbase * (DD / 2) + ks;

    const int len = (ks < 4) ? 63 : 62;   // kk = ks + 8s < 500

    #pragma unroll 2
    for (int s = 0; s < len; s++) {
        const int kk = s * 8;
        unsigned long long w[8], x[4];
        #pragma unroll
        for (int j = 0; j < 8; j++) w[j] = wp[j * (WS / 2) + kk];
        #pragma unroll
        for (int i = 0; i < 4; i++) x[i] = xp[i * 4 * (DD / 2) + kk];
        #pragma unroll
        for (int i = 0; i < 4; i++)
            #pragma unroll
            for (int j = 0; j < 8; j++)
                ffma2(acc[i][j], x[i], w[j]);
    }

    // ---- reduce packed halves + across 8 k-split lanes (xor 1,2,4) ----
    #pragma unroll
    for (int i = 0; i < 4; i++) {
        #pragma unroll
        for (int j = 0; j < 8; j++) {
            const unsigned long long a = acc[i][j];
            float v = __uint_as_float((unsigned)(a & 0xffffffffull)) +
                      __uint_as_float((unsigned)(a >> 32));
            v += __shfl_xor_sync(0xffffffffu, v, 1);
            v += __shfl_xor_sync(0xffffffffu, v, 2);
            v += __shfl_xor_sync(0xffffffffu, v, 4);
            if (ks == 0) {
                const int c = cbase + j;
                if (c < CC) {
                    const int t = t0 + ltbase + 4 * i;
                    out[(long long)t * CC + c] = v + bias[c];
                }
            }
        }
    }
}

// ============================================================
extern "C" void kernel_launch(void* const* d_in, const int* in_sizes, int n_in,
                              void* d_out, int out_size)
{
    const int*   ng_ids  = (const int*)d_in[0];
    const int*   ng_mask = (const int*)d_in[1];
    const int*   cx_ids  = (const int*)d_in[2];
    const int*   cx_mask = (const int*)d_in[3];
    const float* embed   = (const float*)d_in[4];
    const float* W       = (const float*)d_in[5];
    const float* bias    = (const float*)d_in[6];
    float*       out     = (float*)d_out;

    feat_kernel<<<BSN, 128>>>(ng_ids, ng_mask, cx_ids, cx_mask, embed);

    const size_t smem = (size_t)(CPAD * WS + (TT + 4) * DD) * sizeof(float); // 221,184 B
    cudaFuncSetAttribute(gemm_kernel, cudaFuncAttributeMaxDynamicSharedMemorySize, (int)smem);
    gemm_kernel<<<BSN / TT, NT2, smem>>>(W, bias, out);
}

// round 5
// speedup vs baseline: 1.3341x; 1.1511x over previous
#include <cuda_runtime.h>

#define VV   400000
#define DD   200
#define CC   45
#define BSN  4096      // B*S
#define SS   128       // S (window padding is per-sequence)
#define KN   12
#define KC   10
#define KT   22
#define F5   1000      // 5*D
#define KQ   250       // F5/4 float4 per window

// ---- kernel 2 tiling ----
#define TT    32       // tokens per block (128 blocks; 32 divides 128)
#define CPAD  48
#define WF4   256      // W row stride in float4 (4096B -> power of 2, no div)
#define XF4   50       // X row stride in float4 (200 floats)
#define NT2   384      // 12 warps: 6 c-groups x 2 t-halves

// scratch: feat [4096, 200]
__device__ float g_feat[BSN * DD];

// ============================================================
// Kernel 1: masked gather + mean  -> g_feat
// ============================================================
__global__ __launch_bounds__(128) void feat_kernel(
    const int* __restrict__ ng_ids, const int* __restrict__ ng_mask,
    const int* __restrict__ cx_ids, const int* __restrict__ cx_mask,
    const float* __restrict__ embed)
{
    const int tok = blockIdx.x;
    const int tid = threadIdx.x;

    __shared__ int raw_ids[KT], raw_msk[KT];
    __shared__ int s_ids[KT];
    __shared__ int s_n;
    __shared__ float s_inv;

    if (tid < KN) {
        raw_ids[tid] = ng_ids[tok * KN + tid];
        raw_msk[tid] = ng_mask[tok * KN + tid];
    } else if (tid < KT) {
        const int j = tid - KN;
        raw_ids[tid] = cx_ids[tok * KC + j];
        raw_msk[tid] = cx_mask[tok * KC + j];
    }
    __syncthreads();

    if (tid == 0) {
        int n = 0;
        #pragma unroll
        for (int i = 0; i < KT; i++)
            if (raw_msk[i]) s_ids[n++] = raw_ids[i];
        s_n = n;
        s_inv = 1.0f / (float)(n > 0 ? n : 1);
    }
    __syncthreads();

    const int n = s_n;
    const float inv = s_inv;

    if (tid < DD / 2) {
        float sx = 0.f, sy = 0.f;
        #pragma unroll 4
        for (int i = 0; i < n; i++) {
            const long long row = (long long)s_ids[i] * DD;
            const float2 v = *(const float2*)&embed[row + tid * 2];
            sx += v.x; sy += v.y;
        }
        *(float2*)&g_feat[(long long)tok * DD + tid * 2] = make_float2(sx * inv, sy * inv);
    }
}

// ============================================================
// Kernel 2: windowed matmul with crossbar-optimal LDS.128
//   warp = 8 ks-lanes x 4 t-groups; thread tile = 8c x 4t
//   w LDS.128: 8 consecutive float4 + 4-way broadcast -> 1 phase
//   x LDS.128: 32 distinct float4, 4 lanes/bank-group -> 4-phase floor
// ============================================================
__device__ __forceinline__ void ffma2(unsigned long long& d,
                                      unsigned long long a,
                                      unsigned long long b)
{
    asm volatile("fma.rn.f32x2 %0, %1, %2, %0;" : "+l"(d) : "l"(a), "l"(b));
}

extern __shared__ float smem2[];

__global__ __launch_bounds__(NT2, 1) void gemm_kernel(
    const float* __restrict__ W, const float* __restrict__ bias,
    float* __restrict__ out)
{
    float* sW = smem2;                        // CPAD * WF4 float4
    float* sX = smem2 + CPAD * WF4 * 4;       // 36 rows * XF4 float4

    const int tid = threadIdx.x;
    const int t0  = blockIdx.x * TT;
    const int b0  = t0 / SS;                  // sequence index of this tile

    // ---- fill W: [48 rows x 256 f4], zero-padded; div-free indexing ----
    {
        float4*       sW4 = (float4*)sW;
        const float4* W4  = (const float4*)W;           // [45, 250] f4
        #pragma unroll
        for (int it = 0; it < (CPAD * WF4) / NT2; it++) {   // 32 iters
            const int i   = it * NT2 + tid;
            const int row = i >> 8;                     // /WF4
            const int q   = i & (WF4 - 1);
            float4 v = make_float4(0.f, 0.f, 0.f, 0.f);
            if (row < CC && q < KQ) v = W4[row * KQ + q];
            sW4[i] = v;
        }
    }

    // ---- fill X tile (+-2 halo rows), zero outside this sequence ----
    {
        float4*       sX4   = (float4*)sX;
        const float4* feat4 = (const float4*)g_feat;
        #pragma unroll
        for (int it = 0; it < (36 * 64) / NT2; it++) {      // 6 iters
            const int i   = it * NT2 + tid;
            const int row = i >> 6;
            const int col = i & 63;
            if (col < XF4) {
                const int g  = t0 + row - 2;
                const bool ok = ((g >> 7) == b0);       // same sequence only
                sX4[row * XF4 + col] = ok
                    ? feat4[(long long)g * XF4 + col]
                    : make_float4(0.f, 0.f, 0.f, 0.f);
            }
        }
    }
    __syncthreads();

    // ---- decomposition ----
    const int lane = tid & 31;
    const int wrp  = tid >> 5;       // 0..11
    const int ks   = lane & 7;       // k-split lane (f4 chunks ks + 8s)
    const int g    = lane >> 3;      // t-group, 0..3
    const int cg   = wrp % 6;        // c group (8 c's)
    const int th   = wrp / 6;        // t half
    const int cbase  = cg * 8;
    const int ltbase = th * 16 + g;  // tokens ltbase + 4*i

    unsigned long long acc[4][8];
    #pragma unroll
    for (int i = 0; i < 4; i++)
        #pragma unroll
        for (int j = 0; j < 8; j++) acc[i][j] = 0ull;

    const ulonglong2* wp = (const ulonglong2*)sW + (long long)cbase * WF4 + ks;
    const ulonglong2* xp = (const ulonglong2*)sX + (long long)ltbase * XF4 + ks;

    const int len = (KQ - ks + 7) >> 3;          // 32 for ks<2, else 31

    #pragma unroll 1
    for (int s = 0; s < len; s++) {
        const int q = s * 8;
        ulonglong2 x[4];
        #pragma unroll
        for (int i = 0; i < 4; i++) x[i] = xp[i * (4 * XF4) + q];

        ulonglong2 w[4];
        #pragma unroll
        for (int j = 0; j < 4; j++) w[j] = wp[j * WF4 + q];
        #pragma unroll
        for (int i = 0; i < 4; i++)
            #pragma unroll
            for (int j = 0; j < 4; j++) {
                ffma2(acc[i][j], x[i].x, w[j].x);
                ffma2(acc[i][j], x[i].y, w[j].y);
            }

        #pragma unroll
        for (int j = 0; j < 4; j++) w[j] = wp[(j + 4) * WF4 + q];
        #pragma unroll
        for (int i = 0; i < 4; i++)
            #pragma unroll
            for (int j = 0; j < 4; j++) {
                ffma2(acc[i][j + 4], x[i].x, w[j].x);
                ffma2(acc[i][j + 4], x[i].y, w[j].y);
            }
    }

    // ---- reduce packed halves + across 8 ks lanes ----
    #pragma unroll
    for (int i = 0; i < 4; i++) {
        #pragma unroll
        for (int j = 0; j < 8; j++) {
            const unsigned long long a = acc[i][j];
            float v = __uint_as_float((unsigned)(a & 0xffffffffull)) +
                      __uint_as_float((unsigned)(a >> 32));
            v += __shfl_xor_sync(0xffffffffu, v, 1);
            v += __shfl_xor_sync(0xffffffffu, v, 2);
            v += __shfl_xor_sync(0xffffffffu, v, 4);
            if (ks == 0) {
                const int c = cbase + j;
                if (c < CC) {
                    const int t = t0 + ltbase + 4 * i;
                    out[(long long)t * CC + c] = v + bias[c];
                }
            }
        }
    }
}

// ============================================================
extern "C" void kernel_launch(void* const* d_in, const int* in_sizes, int n_in,
                              void* d_out, int out_size)
{
    const int*   ng_ids  = (const int*)d_in[0];
    const int*   ng_mask = (const int*)d_in[1];
    const int*   cx_ids  = (const int*)d_in[2];
    const int*   cx_mask = (const int*)d_in[3];
    const float* embed   = (const float*)d_in[4];
    const float* W       = (const float*)d_in[5];
    const float* bias    = (const float*)d_in[6];
    float*       out     = (float*)d_out;

    feat_kernel<<<BSN, 128>>>(ng_ids, ng_mask, cx_ids, cx_mask, embed);

    const size_t smem = (size_t)(CPAD * WF4 * 4 + 36 * XF4 * 4) * sizeof(float); // 225,408 B
    cudaFuncSetAttribute(gemm_kernel, cudaFuncAttributeMaxDynamicSharedMemorySize, (int)smem);
    gemm_kernel<<<BSN / TT, NT2, smem>>>(W, bias, out);
}